// round 17
// baseline (speedup 1.0000x reference)
#include <cuda_runtime.h>
#include <cuda_bf16.h>
#include <cstdint>

#define NN 20000
#define EE 320000
#define GG 200
#define FF 128

// ---- scratch (static device globals: allocation-free at runtime) ----
__device__ float g_x[NN * FF];            // node features
__device__ float g_P[NN * 768];           // per-node gate/mlp projections
__device__ float g_Y[NN * 384];           // per-node [y_p1|y_p2|y_psi]
__device__ float g_pool[GG * FF];         // accumulated pools
__device__ unsigned g_xH[NN * 64];        // x hi bf16, word-packed (2 bf16/word, k-contig)
__device__ unsigned g_xL[NN * 64];        // x lo bf16
__device__ unsigned g_BcatH[3 * 768 * 64];   // [i][out-row][kw]
__device__ unsigned g_BcatL[3 * 768 * 64];
__device__ unsigned g_BpoolH[3 * 384 * 64];
__device__ unsigned g_BpoolL[3 * 384 * 64];
__device__ unsigned g_WembH[128 * 64];
__device__ unsigned g_WembL[128 * 64];

typedef unsigned long long ull;

__device__ __forceinline__ float sigm(float v) { return 1.0f / (1.0f + __expf(-v)); }
__device__ __forceinline__ float eluf(float v) { return v > 0.f ? v : (__expf(v) - 1.0f); }

__device__ __forceinline__ void fma2(ull& acc, ull a, ull b) {
    asm("fma.rn.f32x2 %0, %1, %2, %0;" : "+l"(acc) : "l"(a), "l"(b));
}
__device__ __forceinline__ ull mul2(ull a, ull b) {
    ull r; asm("mul.rn.f32x2 %0, %1, %2;" : "=l"(r) : "l"(a), "l"(b)); return r;
}
__device__ __forceinline__ float2 unp(ull v) {
    float2 r; asm("mov.b64 {%0,%1}, %2;" : "=f"(r.x), "=f"(r.y) : "l"(v)); return r;
}
__device__ __forceinline__ ull pk(float a, float b) {
    ull r; asm("mov.b64 %0, {%1,%2};" : "=l"(r) : "f"(a), "f"(b)); return r;
}

__device__ __forceinline__ void red_add_v4(float* addr, float a, float b, float c, float d) {
    asm volatile("red.global.add.v4.f32 [%0], {%1, %2, %3, %4};"
                 :: "l"(addr), "f"(a), "f"(b), "f"(c), "f"(d) : "memory");
}

__device__ __forceinline__ unsigned pack_bf2(float v0, float v1) {
    __nv_bfloat162 t;
    t.x = __float2bfloat16(v0);
    t.y = __float2bfloat16(v1);
    return *reinterpret_cast<unsigned*>(&t);
}
__device__ __forceinline__ void split2(float v0, float v1, unsigned* h, unsigned* l) {
    float h0 = __bfloat162float(__float2bfloat16(v0));
    float h1 = __bfloat162float(__float2bfloat16(v1));
    *h = pack_bf2(v0, v1);
    *l = pack_bf2(v0 - h0, v1 - h1);
}

// mma.sync m16n8k16 row.col bf16 -> f32 accumulate (in-place into c[4])
#define MMA16816(c, a0, a1, a2, a3, b0, b1) \
    asm("mma.sync.aligned.m16n8k16.row.col.f32.bf16.bf16.f32 " \
        "{%0,%1,%2,%3}, {%4,%5,%6,%7}, {%8,%9}, {%0,%1,%2,%3};" \
        : "+f"((c)[0]), "+f"((c)[1]), "+f"((c)[2]), "+f"((c)[3]) \
        : "r"(a0), "r"(a1), "r"(a2), "r"(a3), "r"(b0), "r"(b1))

// =====================================================================
// Split conversion: fp32 [nwords*2] -> hi/lo bf16 word-packed
// =====================================================================
__global__ void cvt_split_kernel(const float* __restrict__ X,
                                 unsigned* __restrict__ H, unsigned* __restrict__ L, int nwords)
{
    int i = blockIdx.x * blockDim.x + threadIdx.x;
    if (i >= nwords) return;
    float2 v = *(const float2*)(X + (size_t)i * 2);
    split2(v.x, v.y, H + i, L + i);
}

// =====================================================================
// Weight packing: [in=128, out] fp32 -> [out-row][kword] hi/lo bf16
// =====================================================================
__global__ void packW_gates_kernel(const float* __restrict__ Wg, const float* __restrict__ Wm)
{
    int idx = blockIdx.x * blockDim.x + threadIdx.x;
    if (idx >= 3 * 768 * 64) return;
    int kw = idx & 63;
    int j = (idx >> 6) % 768;
    int i = idx / (64 * 768);
    int b = j >> 7;
    int c = j & 127;
    const float* src;
    if (b < 3) src = Wg + ((size_t)i * 384 + (size_t)b * 128) * 128;
    else       src = Wm + ((size_t)i * 384 + (size_t)(b - 3) * 128) * 128;
    float v0 = src[(size_t)(kw * 2) * 128 + c];
    float v1 = src[(size_t)(kw * 2 + 1) * 128 + c];
    split2(v0, v1, &g_BcatH[idx], &g_BcatL[idx]);
}

__global__ void packW_pool_kernel(const float* __restrict__ Wp1, const float* __restrict__ Wp2,
                                  const float* __restrict__ Wpsi)
{
    int idx = blockIdx.x * blockDim.x + threadIdx.x;
    if (idx >= 3 * 384 * 64) return;
    int kw = idx & 63;
    int j = (idx >> 6) % 384;
    int i = idx / (64 * 384);
    int b = j >> 7;
    int c = j & 127;
    const float* W;
    if (b == 0) W = Wp1; else if (b == 1) W = Wp2; else W = Wpsi;
    W += (size_t)i * 128 * 128;
    float v0 = W[(size_t)(kw * 2) * 128 + c];
    float v1 = W[(size_t)(kw * 2 + 1) * 128 + c];
    split2(v0, v1, &g_BpoolH[idx], &g_BpoolL[idx]);
}

__global__ void packW_emb_kernel(const float* __restrict__ Wemb)
{
    int idx = blockIdx.x * blockDim.x + threadIdx.x;
    if (idx >= 128 * 64) return;
    int kw = idx & 63;
    int c = idx >> 6;
    float v0 = Wemb[(size_t)(kw * 2) * 128 + c];
    float v1 = Wemb[(size_t)(kw * 2 + 1) * 128 + c];
    split2(v0, v1, &g_WembH[idx], &g_WembL[idx]);
}

__global__ void zero_pool_kernel()
{
    int i = blockIdx.x * blockDim.x + threadIdx.x;
    if (i < GG * FF) g_pool[i] = 0.f;
}

// =====================================================================
// Tensor-core GEMM via mma.sync (HMMA), split-bf16 3-term:
//   C[M,Ntot tile 64x128] = act( Ah@Bh^T + Al@Bh^T + Ah@Bl^T )
// A: [M][64w] hi/lo word-packed k-contig. B: [Nrows][64w] likewise.
// 8 warps: mi = w&1 (2 x 32 rows), ni = w>>2? -> w>>1 (4 x 32 cols).
// No shared memory; fragments loaded directly from global (L1/L2-hot).
// =====================================================================
__global__ __launch_bounds__(256) void gemmMMA_kernel(
    const unsigned* __restrict__ Ah, const unsigned* __restrict__ Al,
    const unsigned* __restrict__ Bh, const unsigned* __restrict__ Bl,
    float* __restrict__ C, int M, int Ntot, int act)
{
    int tid = threadIdx.x;
    int lane = tid & 31;
    int w = tid >> 5;
    int g = lane >> 2;          // 0..7
    int tig = lane & 3;         // 0..3
    int mi = w & 1;
    int ni = w >> 1;            // 0..3
    int m0 = blockIdx.x * 64 + mi * 32;
    int n0 = blockIdx.y * 128 + ni * 32;

    // 4 distinct A rows per thread: subtile ms uses rows mr[2ms], mr[2ms+1]
    int mr[4];
    mr[0] = m0 + g;      mr[1] = m0 + g + 8;
    mr[2] = m0 + g + 16; mr[3] = m0 + g + 24;
    bool mok[4];
    #pragma unroll
    for (int j = 0; j < 4; j++) mok[j] = (mr[j] < M);

    float c[2][4][4];
    #pragma unroll
    for (int ms = 0; ms < 2; ms++)
        #pragma unroll
        for (int ns = 0; ns < 4; ns++)
            #pragma unroll
            for (int q = 0; q < 4; q++) c[ms][ns][q] = 0.f;

    #pragma unroll 2
    for (int kc = 0; kc < 8; kc++) {
        int kw0 = kc * 8 + tig;
        int kw1 = kw0 + 4;

        unsigned aH[2][4], aL[2][4];
        #pragma unroll
        for (int ms = 0; ms < 2; ms++) {
            size_t r0 = (size_t)mr[ms * 2] * 64;
            size_t r1 = (size_t)mr[ms * 2 + 1] * 64;
            bool ok0 = mok[ms * 2], ok1 = mok[ms * 2 + 1];
            aH[ms][0] = ok0 ? Ah[r0 + kw0] : 0u;
            aH[ms][1] = ok1 ? Ah[r1 + kw0] : 0u;
            aH[ms][2] = ok0 ? Ah[r0 + kw1] : 0u;
            aH[ms][3] = ok1 ? Ah[r1 + kw1] : 0u;
            aL[ms][0] = ok0 ? Al[r0 + kw0] : 0u;
            aL[ms][1] = ok1 ? Al[r1 + kw0] : 0u;
            aL[ms][2] = ok0 ? Al[r0 + kw1] : 0u;
            aL[ms][3] = ok1 ? Al[r1 + kw1] : 0u;
        }
        unsigned bH[4][2], bL[4][2];
        #pragma unroll
        for (int ns = 0; ns < 4; ns++) {
            size_t nrow = (size_t)(n0 + ns * 8 + g) * 64;
            bH[ns][0] = Bh[nrow + kw0];
            bH[ns][1] = Bh[nrow + kw1];
            bL[ns][0] = Bl[nrow + kw0];
            bL[ns][1] = Bl[nrow + kw1];
        }
        #pragma unroll
        for (int ms = 0; ms < 2; ms++)
            #pragma unroll
            for (int ns = 0; ns < 4; ns++) {
                MMA16816(c[ms][ns], aH[ms][0], aH[ms][1], aH[ms][2], aH[ms][3], bH[ns][0], bH[ns][1]);
                MMA16816(c[ms][ns], aL[ms][0], aL[ms][1], aL[ms][2], aL[ms][3], bH[ns][0], bH[ns][1]);
                MMA16816(c[ms][ns], aH[ms][0], aH[ms][1], aH[ms][2], aH[ms][3], bL[ns][0], bL[ns][1]);
            }
    }

    // epilogue: c0,c1 -> row mr[2ms], cols 2tig,2tig+1; c2,c3 -> row mr[2ms+1]
    #pragma unroll
    for (int ms = 0; ms < 2; ms++) {
        #pragma unroll
        for (int ns = 0; ns < 4; ns++) {
            int col = n0 + ns * 8 + tig * 2;
            float v0 = c[ms][ns][0], v1 = c[ms][ns][1];
            float v2 = c[ms][ns][2], v3 = c[ms][ns][3];
            if (act == 1) { v0 = sigm(v0); v1 = sigm(v1); v2 = sigm(v2); v3 = sigm(v3); }
            if (mok[ms * 2])
                *(float2*)(C + (size_t)mr[ms * 2] * Ntot + col) = make_float2(v0, v1);
            if (mok[ms * 2 + 1])
                *(float2*)(C + (size_t)mr[ms * 2 + 1] * Ntot + col) = make_float2(v2, v3);
        }
    }
}

// =====================================================================
// Edge kernel (R16-proven): 64-edge tiles, 8 edges/warp, merged A+B.
// =====================================================================
__global__ __launch_bounds__(256) void edge_kernel(
    const int* __restrict__ esrc, const int* __restrict__ etgt,
    const float* __restrict__ edist,
    const float* __restrict__ cs, const float* __restrict__ pw,
    const float* __restrict__ W1v, const float* __restrict__ W2v,
    const float* __restrict__ W2vg, int E)
{
    extern __shared__ float smem[];
    float* sW = smem;                 // 88*128 floats = 45056 B
    float* sC = smem + 88 * 128;      // [64 edges][64 kslots] plain = 16384 B

    for (int i = threadIdx.x; i < 36 * 128; i += 256) sW[i] = W1v[i];
    for (int i = threadIdx.x; i < 26 * 128; i += 256) sW[36 * 128 + i] = W2v[i];
    for (int i = threadIdx.x; i < 26 * 128; i += 256) sW[62 * 128 + i] = W2vg[i];
    __syncthreads();

    int tid = threadIdx.x;
    int lane = tid & 31;
    int warp = tid >> 5;
    int f0 = lane * 4;
    int eb = warp * 8;
    int ntiles = (E + 63) >> 6;

    for (int tile = blockIdx.x; tile < ntiles; tile += gridDim.x) {
        int e0 = tile * 64;
        for (int idx = tid; idx < 64 * 36; idx += 256) {
            int e = idx / 36, k = idx % 36;
            if (e0 + e < E) sC[e * 64 + k] = cs[(size_t)(e0 + e) * 36 + k];
        }
        for (int idx = tid; idx < 64 * 26; idx += 256) {
            int e = idx / 26, k = idx % 26;
            if (e0 + e < E) sC[e * 64 + 36 + k] = pw[(size_t)(e0 + e) * 26 + k];
        }
        __syncthreads();

        ull zg[8][2], za[8][2];
        #pragma unroll
        for (int e = 0; e < 8; e++) {
            zg[e][0] = 0ull; zg[e][1] = 0ull;
            za[e][0] = 0ull; za[e][1] = 0ull;
        }
        for (int kc = 0; kc < 13; kc++) {
            float4 g0 = *(float4*)(&sW[(62 + kc * 2) * 128 + f0]);
            float4 g1 = *(float4*)(&sW[(63 + kc * 2) * 128 + f0]);
            float4 v0 = *(float4*)(&sW[(36 + kc * 2) * 128 + f0]);
            float4 v1 = *(float4*)(&sW[(37 + kc * 2) * 128 + f0]);
            ull g0a = ((ull*)&g0)[0], g0b = ((ull*)&g0)[1];
            ull g1a = ((ull*)&g1)[0], g1b = ((ull*)&g1)[1];
            ull v0a = ((ull*)&v0)[0], v0b = ((ull*)&v0)[1];
            ull v1a = ((ull*)&v1)[0], v1b = ((ull*)&v1)[1];
            #pragma unroll
            for (int e = 0; e < 8; e++) {
                float2 cc = *(float2*)(&sC[(eb + e) * 64 + 36 + kc * 2]);
                ull c0 = pk(cc.x, cc.x);
                ull c1 = pk(cc.y, cc.y);
                fma2(zg[e][0], c0, g0a); fma2(zg[e][1], c0, g0b);
                fma2(zg[e][0], c1, g1a); fma2(zg[e][1], c1, g1b);
                fma2(za[e][0], c0, v0a); fma2(za[e][1], c0, v0b);
                fma2(za[e][0], c1, v1a); fma2(za[e][1], c1, v1b);
            }
        }
        #pragma unroll
        for (int e = 0; e < 8; e++) {
            #pragma unroll
            for (int h = 0; h < 2; h++) {
                float2 v = unp(zg[e][h]);
                za[e][h] = mul2(za[e][h], pk(sigm(v.x), sigm(v.y)));
            }
        }

        for (int kc = 0; kc < 18; kc++) {
            float4 w0 = *(float4*)(&sW[(kc * 2) * 128 + f0]);
            float4 w1 = *(float4*)(&sW[(kc * 2 + 1) * 128 + f0]);
            ull w0a = ((ull*)&w0)[0], w0b = ((ull*)&w0)[1];
            ull w1a = ((ull*)&w1)[0], w1b = ((ull*)&w1)[1];
            #pragma unroll
            for (int e = 0; e < 8; e++) {
                float2 cc = *(float2*)(&sC[(eb + e) * 64 + kc * 2]);
                ull c0 = pk(cc.x, cc.x);
                ull c1 = pk(cc.y, cc.y);
                fma2(za[e][0], c0, w0a); fma2(za[e][1], c0, w0b);
                fma2(za[e][0], c1, w1a); fma2(za[e][1], c1, w1b);
            }
        }

        int sreg = 0, treg = 0; float dreg = 1.f;
        if (lane < 8 && (e0 + eb + lane) < E) {
            sreg = esrc[e0 + eb + lane];
            treg = etgt[e0 + eb + lane];
            dreg = edist[e0 + eb + lane];
        }
        #pragma unroll
        for (int e = 0; e < 8; e++) {
            int s = __shfl_sync(0xffffffffu, sreg, e);
            int t = __shfl_sync(0xffffffffu, treg, e);
            float invd = 1.0f / __shfl_sync(0xffffffffu, dreg, e);
            if ((e0 + eb + e) < E) {
                const float* Ps = g_P + (size_t)s * 768;
                const float* Pt = g_P + (size_t)t * 768;
                float4 ag  = *(const float4*)(Ps + f0);
                float4 bg  = *(const float4*)(Pt + 128 + f0);
                float4 cgs = *(const float4*)(Ps + 256 + f0);
                float4 cgt = *(const float4*)(Pt + 256 + f0);
                float4 am  = *(const float4*)(Ps + 384 + f0);
                float4 bm  = *(const float4*)(Pt + 512 + f0);
                float4 cms = *(const float4*)(Ps + 640 + f0);
                float4 cmt = *(const float4*)(Pt + 640 + f0);

                float2 za0 = unp(za[e][0]);
                float2 za1 = unp(za[e][1]);
                float zv[4] = { za0.x, za0.y, za1.x, za1.y };
                float gv[4], mv[4];
                gv[0] = sigm(ag.x + bg.x + (cgt.x - cgs.x) * invd);
                gv[1] = sigm(ag.y + bg.y + (cgt.y - cgs.y) * invd);
                gv[2] = sigm(ag.z + bg.z + (cgt.z - cgs.z) * invd);
                gv[3] = sigm(ag.w + bg.w + (cgt.w - cgs.w) * invd);
                mv[0] = eluf(am.x + bm.x + (cmt.x - cms.x) * invd);
                mv[1] = eluf(am.y + bm.y + (cmt.y - cms.y) * invd);
                mv[2] = eluf(am.z + bm.z + (cmt.z - cms.z) * invd);
                mv[3] = eluf(am.w + bm.w + (cmt.w - cms.w) * invd);

                red_add_v4(g_x + (size_t)s * 128 + f0,
                           gv[0] * mv[0] * zv[0], gv[1] * mv[1] * zv[1],
                           gv[2] * mv[2] * zv[2], gv[3] * mv[3] * zv[3]);
            }
        }
        __syncthreads();
    }
}

// =====================================================================
// Pool + psi: per node, pool[g] += elu(y1)*y2 ; x = elu(y3)
// =====================================================================
__global__ __launch_bounds__(256) void poolpsi_kernel(const int* __restrict__ gidx, int N)
{
    int lane = threadIdx.x & 31;
    int f0 = lane * 4;
    int warp = blockIdx.x * 8 + (threadIdx.x >> 5);
    int nw = gridDim.x * 8;
    for (int n = warp; n < N; n += nw) {
        int g = gidx[n];
        const float* yr = g_Y + (size_t)n * 384;
        float y1[4], y2[4], y3[4];
        *(float4*)y1 = *(const float4*)(yr + f0);
        *(float4*)y2 = *(const float4*)(yr + 128 + f0);
        *(float4*)y3 = *(const float4*)(yr + 256 + f0);
        red_add_v4(g_pool + (size_t)g * 128 + f0,
                   eluf(y1[0]) * y2[0], eluf(y1[1]) * y2[1],
                   eluf(y1[2]) * y2[2], eluf(y1[3]) * y2[3]);
        float xo[4];
        #pragma unroll
        for (int j = 0; j < 4; j++) xo[j] = eluf(y3[j]);
        *(float4*)(g_x + (size_t)n * 128 + f0) = *(float4*)xo;
    }
}

// =====================================================================
// Final MLP: one warp per graph.  128 -> 64 -> 42 -> 1
// =====================================================================
__global__ __launch_bounds__(256) void final_kernel(
    const float* __restrict__ W1, const float* __restrict__ W2,
    const float* __restrict__ W3, float* __restrict__ out, int G)
{
    int lane = threadIdx.x & 31;
    int warp = blockIdx.x * 8 + (threadIdx.x >> 5);
    int nw = gridDim.x * 8;
    for (int g = warp; g < G; g += nw) {
        float pr[4];
        #pragma unroll
        for (int c = 0; c < 4; c++) pr[c] = g_pool[(size_t)g * 128 + c * 32 + lane];

        float a0 = 0.f, a1 = 0.f;
        #pragma unroll
        for (int c = 0; c < 4; c++) {
            #pragma unroll
            for (int kk = 0; kk < 32; kk++) {
                float v = __shfl_sync(0xffffffffu, pr[c], kk);
                int k = c * 32 + kk;
                a0 += v * W1[k * 64 + lane * 2];
                a1 += v * W1[k * 64 + lane * 2 + 1];
            }
        }
        a0 = eluf(a0); a1 = eluf(a1);

        float b0 = 0.f, b1 = 0.f;
        #pragma unroll
        for (int k = 0; k < 64; k++) {
            float v = __shfl_sync(0xffffffffu, (k & 1) ? a1 : a0, k >> 1);
            b0 += v * W2[k * 42 + lane];
            if (lane < 10) b1 += v * W2[k * 42 + 32 + lane];
        }
        b0 = eluf(b0);
        if (lane < 10) b1 = eluf(b1);

        float r = b0 * W3[lane] + ((lane < 10) ? b1 * W3[32 + lane] : 0.f);
        #pragma unroll
        for (int o = 16; o; o >>= 1) r += __shfl_xor_sync(0xffffffffu, r, o);
        if (lane == 0) out[g] = r;
    }
}

// =====================================================================
extern "C" void kernel_launch(void* const* d_in, const int* in_sizes, int n_in,
                              void* d_out, int out_size)
{
    (void)n_in; (void)out_size;
    const float* nodes  = (const float*)d_in[0];
    const int*   esrc   = (const int*)d_in[1];
    const int*   etgt   = (const int*)d_in[2];
    const float* edist  = (const float*)d_in[3];
    const int*   gidx   = (const int*)d_in[4];
    const float* cs     = (const float*)d_in[6];
    const float* pw     = (const float*)d_in[7];
    const float* W_emb  = (const float*)d_in[8];
    const float* Wg     = (const float*)d_in[9];
    const float* Wm     = (const float*)d_in[10];
    const float* W1v    = (const float*)d_in[11];
    const float* W2v    = (const float*)d_in[12];
    const float* W2vg   = (const float*)d_in[13];
    const float* Wp1    = (const float*)d_in[14];
    const float* Wp2    = (const float*)d_in[15];
    const float* Wpsi   = (const float*)d_in[16];
    const float* Wlr1   = (const float*)d_in[17];
    const float* Wlr2   = (const float*)d_in[18];
    const float* Wlr3   = (const float*)d_in[19];
    float* out = (float*)d_out;

    int N = in_sizes[0] / FF;       // 20000
    int E = in_sizes[1];            // 320000
    int G = in_sizes[5];            // 200

    float *px, *pP, *pY;
    unsigned *pxH, *pxL, *pBcatH, *pBcatL, *pBpoolH, *pBpoolL, *pWembH, *pWembL;
    cudaGetSymbolAddress((void**)&px, g_x);
    cudaGetSymbolAddress((void**)&pP, g_P);
    cudaGetSymbolAddress((void**)&pY, g_Y);
    cudaGetSymbolAddress((void**)&pxH, g_xH);
    cudaGetSymbolAddress((void**)&pxL, g_xL);
    cudaGetSymbolAddress((void**)&pBcatH, g_BcatH);
    cudaGetSymbolAddress((void**)&pBcatL, g_BcatL);
    cudaGetSymbolAddress((void**)&pBpoolH, g_BpoolH);
    cudaGetSymbolAddress((void**)&pBpoolL, g_BpoolL);
    cudaGetSymbolAddress((void**)&pWembH, g_WembH);
    cudaGetSymbolAddress((void**)&pWembL, g_WembL);

    static int smem_set = 0;
    const int EDGE_SMEM = 88 * 128 * 4 + 64 * 64 * 4;  // 61440 B
    if (!smem_set) {
        cudaFuncSetAttribute(edge_kernel, cudaFuncAttributeMaxDynamicSharedMemorySize, EDGE_SMEM);
        smem_set = 1;
    }

    int xwords = N * 64;

    // prep: weight packs + pool zero + node split
    packW_gates_kernel<<<(3 * 768 * 64 + 255) / 256, 256>>>(Wg, Wm);
    packW_pool_kernel<<<(3 * 384 * 64 + 255) / 256, 256>>>(Wp1, Wp2, Wpsi);
    packW_emb_kernel<<<(128 * 64 + 255) / 256, 256>>>(W_emb);
    zero_pool_kernel<<<(GG * FF + 255) / 256, 256>>>();
    cvt_split_kernel<<<(xwords + 255) / 256, 256>>>(nodes, pxH, pxL, xwords);

    int mg = (N + 63) / 64;   // 313

    // embedding: x = sigmoid(nodes @ W_emb)    [N,128] -> 1 col-CTA of 128
    gemmMMA_kernel<<<dim3(mg, 1), 256>>>(pxH, pxL, pWembH, pWembL, px, N, 128, 1);
    cvt_split_kernel<<<(xwords + 255) / 256, 256>>>(px, pxH, pxL, xwords);

    for (int i = 0; i < 3; i++) {
        // P = x @ Bcat[i]   [N, 768] -> 6 col-CTAs
        gemmMMA_kernel<<<dim3(mg, 6), 256>>>(pxH, pxL,
            pBcatH + (size_t)i * 768 * 64, pBcatL + (size_t)i * 768 * 64, pP, N, 768, 0);
        // edge pass: scatter-add z into x
        edge_kernel<<<296, 256, EDGE_SMEM>>>(esrc, etgt, edist, cs, pw,
                                             W1v + (size_t)i * 36 * 128,
                                             W2v + (size_t)i * 26 * 128,
                                             W2vg + (size_t)i * 26 * 128, E);
        cvt_split_kernel<<<(xwords + 255) / 256, 256>>>(px, pxH, pxL, xwords);
        // Y = x @ Bpool[i]  [N, 384] -> 3 col-CTAs
        gemmMMA_kernel<<<dim3(mg, 3), 256>>>(pxH, pxL,
            pBpoolH + (size_t)i * 384 * 64, pBpoolL + (size_t)i * 384 * 64, pY, N, 384, 0);
        // pool accumulation + x = elu(x @ Wpsi)
        poolpsi_kernel<<<625, 256>>>(gidx, N);
        if (i < 2)
            cvt_split_kernel<<<(xwords + 255) / 256, 256>>>(px, pxH, pxL, xwords);
    }

    final_kernel<<<(G + 7) / 8, 256>>>(Wlr1, Wlr2, Wlr3, out, G);
}